// round 16
// baseline (speedup 1.0000x reference)
#include <cuda_runtime.h>
#include <cuda_fp16.h>
#include <cstdint>

#define CB 2
#define CL 2048
#define CE 2048
#define CH 16
#define CHD 128
#define CM (CB*CL)      // 4096
#define C3E (3*CE)      // 6144

// ---------------- scratch (device globals; no allocations allowed) ----------
static __device__ __half g_qh[(size_t)CB*CH*CL*CHD];     // [b,h,l,d] fp16
static __device__ __half g_kh[(size_t)CB*CH*CL*CHD];
static __device__ __half g_vh[(size_t)CB*CH*CL*CHD];
static __device__ __half g_xh[(size_t)CM * CE];          // x in fp16
static __device__ __half g_wah[(size_t)C3E * CE];        // w_attn fp16
static __device__ __half g_wph[(size_t)CE * CE];         // w_proj fp16
static __device__ __half g_yh[(size_t)CM * CE];          // attention out fp16

// ---------------- PTX helpers -------------------------------------------------
__device__ __forceinline__ uint32_t smem_u32(const void* p) {
    uint32_t a;
    asm("{ .reg .u64 t; cvta.to.shared.u64 t, %1; cvt.u32.u64 %0, t; }"
        : "=r"(a) : "l"(p));
    return a;
}
__device__ __forceinline__ void cp16(uint32_t dst, const void* src) {
    asm volatile("cp.async.cg.shared.global [%0], [%1], 16;"
                 :: "r"(dst), "l"(src));
}
#define CP_COMMIT() asm volatile("cp.async.commit_group;" ::: "memory")
#define CP_WAIT(n)  asm volatile("cp.async.wait_group %0;" :: "n"(n) : "memory")

__device__ __forceinline__ void ldsm_x4(uint32_t& r0, uint32_t& r1,
                                        uint32_t& r2, uint32_t& r3, uint32_t a) {
    asm volatile("ldmatrix.sync.aligned.m8n8.x4.shared.b16 {%0,%1,%2,%3}, [%4];"
                 : "=r"(r0), "=r"(r1), "=r"(r2), "=r"(r3) : "r"(a));
}
__device__ __forceinline__ void ldsm_x4t(uint32_t& r0, uint32_t& r1,
                                         uint32_t& r2, uint32_t& r3, uint32_t a) {
    asm volatile("ldmatrix.sync.aligned.m8n8.x4.trans.shared.b16 {%0,%1,%2,%3}, [%4];"
                 : "=r"(r0), "=r"(r1), "=r"(r2), "=r"(r3) : "r"(a));
}
__device__ __forceinline__ void mma16816(float* c, const uint32_t* a,
                                         const uint32_t* b) {
    asm volatile("mma.sync.aligned.m16n8k16.row.col.f32.f16.f16.f32 "
                 "{%0,%1,%2,%3}, {%4,%5,%6,%7}, {%8,%9}, {%0,%1,%2,%3};"
                 : "+f"(c[0]), "+f"(c[1]), "+f"(c[2]), "+f"(c[3])
                 : "r"(a[0]), "r"(a[1]), "r"(a[2]), "r"(a[3]),
                   "r"(b[0]), "r"(b[1]));
}
__device__ __forceinline__ float ex2f(float x) {
    float y;
    asm("ex2.approx.ftz.f32 %0, %1;" : "=f"(y) : "f"(x));
    return y;
}

// ---------------- GEMM common: 128x256 CTA tile, warp tile 64x64, BK=32 -----
#define BM 128
#define BN 256
#define BK 32
#define ASTR 40
#define STAGES 4
#define ASTAGE (BM * ASTR)                    // 5120 halves
#define BSTAGE (BN * ASTR)                    // 10240 halves
#define STG_HALVES (ASTAGE + BSTAGE)          // 15360
#define GEMM_SMEM (STAGES * STG_HALVES * 2)   // 122880 B

// mainloop producing acc[4][8][4] for warp tile (wm, wn); 64 MMA / 16 ldsm per chunk
// A tile: 128 rows x 4 chunks = 512 cp16 (2/thread); B: 256 x 4 = 1024 (4/thread)
#define GEMM_MAINLOOP(Aptr, Bptr, Kdim)                                        \
    float acc[4][8][4];                                                        \
    _Pragma("unroll")                                                          \
    for (int mt = 0; mt < 4; mt++)                                             \
        _Pragma("unroll")                                                      \
        for (int nt = 0; nt < 8; nt++)                                         \
            _Pragma("unroll")                                                  \
            for (int i = 0; i < 4; i++) acc[mt][nt][i] = 0.f;                  \
    auto load_stage = [&](int s, int kc) {                                     \
        const __half* ap = (Aptr) + kc * BK;                                   \
        const __half* bp = (Bptr) + kc * BK;                                   \
        uint32_t da = smBase + (uint32_t)(s * STG_HALVES) * 2;                 \
        uint32_t db = da + ASTAGE * 2;                                         \
        _Pragma("unroll")                                                      \
        for (int i = 0; i < 2; i++) {                                          \
            int idx = i * 256 + tid;                                           \
            int row = idx >> 2, ch = (idx & 3) * 8;                            \
            cp16(da + (row * ASTR + ch) * 2, ap + (size_t)row * (Kdim) + ch);  \
        }                                                                      \
        _Pragma("unroll")                                                      \
        for (int i = 0; i < 4; i++) {                                          \
            int idx = i * 256 + tid;                                           \
            int row = idx >> 2, ch = (idx & 3) * 8;                            \
            cp16(db + (row * ASTR + ch) * 2, bp + (size_t)row * (Kdim) + ch);  \
        }                                                                      \
    };                                                                         \
    const int nk = (Kdim) / BK;                                                \
    _Pragma("unroll")                                                          \
    for (int s = 0; s < STAGES - 1; s++) { load_stage(s, s); CP_COMMIT(); }    \
    const int lrow = lane & 15;                                                \
    const int lcol = (lane >> 4) * 8;                                          \
    for (int kc = 0; kc < nk; kc++) {                                          \
        if (kc < nk - 2)       CP_WAIT(2);                                     \
        else if (kc == nk - 2) CP_WAIT(1);                                     \
        else                   CP_WAIT(0);                                     \
        __syncthreads();                                                       \
        if (kc + STAGES - 1 < nk) {                                            \
            load_stage((kc + STAGES - 1) & (STAGES - 1), kc + STAGES - 1);     \
            CP_COMMIT();                                                       \
        }                                                                      \
        const uint32_t baseA = smBase + (uint32_t)((kc & (STAGES - 1)) * STG_HALVES) * 2; \
        const uint32_t baseB = baseA + ASTAGE * 2;                             \
        _Pragma("unroll")                                                      \
        for (int ks = 0; ks < 2; ks++) {                                       \
            uint32_t a[4][4], b[4][4];                                         \
            _Pragma("unroll")                                                  \
            for (int mt = 0; mt < 4; mt++) {                                   \
                uint32_t addr = baseA +                                        \
                    ((wm + mt * 16 + lrow) * ASTR + ks * 16 + lcol) * 2;       \
                ldsm_x4(a[mt][0], a[mt][1], a[mt][2], a[mt][3], addr);         \
            }                                                                  \
            _Pragma("unroll")                                                  \
            for (int nh = 0; nh < 4; nh++) {                                   \
                uint32_t addr = baseB +                                        \
                    ((wn + nh * 16 + lrow) * ASTR + ks * 16 + lcol) * 2;       \
                ldsm_x4(b[nh][0], b[nh][1], b[nh][2], b[nh][3], addr);         \
            }                                                                  \
            _Pragma("unroll")                                                  \
            for (int mt = 0; mt < 4; mt++)                                     \
                _Pragma("unroll")                                              \
                for (int nh = 0; nh < 4; nh++) {                               \
                    uint32_t b0[2] = {b[nh][0], b[nh][2]};                     \
                    uint32_t b1[2] = {b[nh][1], b[nh][3]};                     \
                    mma16816(acc[mt][2 * nh],     a[mt], b0);                  \
                    mma16816(acc[mt][2 * nh + 1], a[mt], b1);                  \
                }                                                              \
        }                                                                      \
    }

// ---------------- proj GEMM: C[M,N] = A[M,K]*B[N,K]^T, fp32 out -------------
__global__ __launch_bounds__(256, 1)
void hgemm_mma(const __half* __restrict__ A, const __half* __restrict__ B,
               float* __restrict__ C, int M, int N, int K) {
    extern __shared__ __half smg[];
    const uint32_t smBase = smem_u32(smg);
    const int tid  = threadIdx.x;
    const int lane = tid & 31;
    const int wid  = tid >> 5;
    const int wm   = (wid >> 2) * 64;
    const int wn   = (wid & 3) * 64;
    const int bm   = blockIdx.y * BM;
    const int bn   = blockIdx.x * BN;
    const __half* Ab = A + (size_t)bm * K;
    const __half* Bb = B + (size_t)bn * K;

    GEMM_MAINLOOP(Ab, Bb, K)

    const int tr = lane >> 2;
    const int tc = (lane & 3) * 2;
#pragma unroll
    for (int mt = 0; mt < 4; mt++) {
#pragma unroll
        for (int nt = 0; nt < 8; nt++) {
            int r = bm + wm + mt * 16 + tr;
            int c = bn + wn + nt * 8 + tc;
            *(float2*)(C + (size_t)r * N + c) =
                make_float2(acc[mt][nt][0], acc[mt][nt][1]);
            *(float2*)(C + (size_t)(r + 8) * N + c) =
                make_float2(acc[mt][nt][2], acc[mt][nt][3]);
        }
    }
}

// ---------------- QKV GEMM with fused RoPE + head-split epilogue ------------
// BN=256 tile: which = bn>>11 constant per CTA; head constant per warp.
__global__ __launch_bounds__(256, 1)
void hgemm_qkv(const __half* __restrict__ A, const __half* __restrict__ B,
               const float* __restrict__ ropeg, int M, int N, int K) {
    extern __shared__ __half smg[];
    const uint32_t smBase = smem_u32(smg);
    const int tid  = threadIdx.x;
    const int lane = tid & 31;
    const int wid  = tid >> 5;
    const int wm   = (wid >> 2) * 64;
    const int wn   = (wid & 3) * 64;
    const int bm   = blockIdx.y * BM;
    const int bn   = blockIdx.x * BN;
    const __half* Ab = A + (size_t)bm * K;
    const __half* Bb = B + (size_t)bn * K;

    GEMM_MAINLOOP(Ab, Bb, K)

    const int tr = lane >> 2;
    const int tc = (lane & 3) * 2;
    const int which = bn >> 11;                   // 0=q, 1=k, 2=v
    const int h     = ((bn + wn) >> 7) & 15;      // constant per warp
    __half* dsts = (which == 0) ? g_qh : (which == 1) ? g_kh : g_vh;

#pragma unroll
    for (int mt = 0; mt < 4; mt++) {
#pragma unroll
        for (int rr = 0; rr < 2; rr++) {
            int r = bm + wm + mt * 16 + tr + rr * 8;
            int l = r & (CL - 1);
            int b = r >> 11;
            __half* base = dsts + ((size_t)(b * CH + h) * CL + l) * CHD;
            const float2* rl = (const float2*)(ropeg + (size_t)l * CHD);
#pragma unroll
            for (int nt = 0; nt < 8; nt++) {
                int d = (wn + nt * 8 + tc) & 127;  // dim within head (even)
                float v0 = acc[mt][nt][rr * 2 + 0];
                float v1 = acc[mt][nt][rr * 2 + 1];
                if (which < 2) {
                    float2 sc = rl[d >> 1];        // x=sin, y=cos
                    float o0 = v0 * sc.y - v1 * sc.x;
                    float o1 = v1 * sc.y + v0 * sc.x;
                    *(__half2*)(base + d) = __floats2half2_rn(o0, o1);
                } else {
                    *(__half2*)(base + d) = __floats2half2_rn(v0, v1);
                }
            }
        }
    }
}

// ---------------- fp32 -> fp16 convert ---------------------------------------
__global__ __launch_bounds__(256)
void f32to16(const float* __restrict__ s, __half* __restrict__ d) {
    int i = blockIdx.x * 256 + threadIdx.x;
    float4 v = *(const float4*)(s + (size_t)i * 4);
    __half2 h0 = __floats2half2_rn(v.x, v.y);
    __half2 h1 = __floats2half2_rn(v.z, v.w);
    uint2 o;
    o.x = *(const uint32_t*)&h0;
    o.y = *(const uint32_t*)&h1;
    *(uint2*)(d + (size_t)i * 4) = o;
}

// ---------------- causal flash attention (HMMA fp16, fp32 accum) -------------
// R8 known-good version: single-buffer KV.
#define FBQ 64
#define FBK 64
#define FSTR 136   // halves per smem row (128 + 8 pad)
#define FLASH_SMEM (3 * 64 * FSTR * 2)   // 52224 B

__global__ __launch_bounds__(128)
void flash_mma() {
    extern __shared__ __half smh[];
    __half* Qs = smh;                 // [64][136]
    __half* Ks = Qs + 64 * FSTR;
    __half* Vs = Ks + 64 * FSTR;

    const int qt   = gridDim.x - 1 - blockIdx.x;   // long CTAs first
    const int bh   = blockIdx.y;
    const int tid  = threadIdx.x;
    const int lane = tid & 31;
    const int wq   = tid >> 5;
    const float SCALE2 = 0.08838834764831845f * 1.4426950408889634f;

    const uint32_t sQ = smem_u32(Qs), sK = smem_u32(Ks), sV = smem_u32(Vs);
    const __half* qbase = g_qh + (size_t)bh * CL * CHD + (size_t)qt * FBQ * CHD;
    const __half* kbase = g_kh + (size_t)bh * CL * CHD;
    const __half* vbase = g_vh + (size_t)bh * CL * CHD;

#pragma unroll
    for (int t = 0; t < 8; t++) {
        int id = t * 128 + tid;
        int row = id >> 4, col = (id & 15) * 8;
        cp16(sQ + (row * FSTR + col) * 2, qbase + (size_t)row * CHD + col);
    }
    CP_COMMIT();
    CP_WAIT(0);
    __syncthreads();

    uint32_t qf[8][4];
#pragma unroll
    for (int ks = 0; ks < 8; ks++) {
        uint32_t addr = sQ + ((wq * 16 + (lane & 15)) * FSTR
                              + ks * 16 + (lane >> 4) * 8) * 2;
        ldsm_x4(qf[ks][0], qf[ks][1], qf[ks][2], qf[ks][3], addr);
    }

    float o[16][4];
#pragma unroll
    for (int nt = 0; nt < 16; nt++)
#pragma unroll
        for (int i = 0; i < 4; i++) o[nt][i] = 0.f;
    float M0 = -1e30f, M1 = -1e30f, L0 = 0.f, L1 = 0.f;

    const int qg0 = qt * FBQ + wq * 16 + (lane >> 2);

    for (int kt = 0; kt <= qt; kt++) {
        const __half* kp = kbase + (size_t)kt * FBK * CHD;
        const __half* vp = vbase + (size_t)kt * FBK * CHD;
#pragma unroll
        for (int t = 0; t < 8; t++) {
            int id = t * 128 + tid;
            int row = id >> 4, col = (id & 15) * 8;
            cp16(sK + (row * FSTR + col) * 2, kp + (size_t)row * CHD + col);
            cp16(sV + (row * FSTR + col) * 2, vp + (size_t)row * CHD + col);
        }
        CP_COMMIT();
        CP_WAIT(0);
        __syncthreads();

        float sc[8][4];
#pragma unroll
        for (int j = 0; j < 8; j++)
#pragma unroll
            for (int i = 0; i < 4; i++) sc[j][i] = 0.f;
#pragma unroll
        for (int ks = 0; ks < 8; ks++) {
#pragma unroll
            for (int jn = 0; jn < 4; jn++) {
                uint32_t r0, r1, r2, r3;
                uint32_t addr = sK + ((jn * 16 + (lane & 15)) * FSTR
                                      + ks * 16 + (lane >> 4) * 8) * 2;
                ldsm_x4(r0, r1, r2, r3, addr);
                uint32_t b0[2] = {r0, r2}, b1[2] = {r1, r3};
                mma16816(sc[2 * jn],     qf[ks], b0);
                mma16816(sc[2 * jn + 1], qf[ks], b1);
            }
        }

        if (kt == qt) {
#pragma unroll
            for (int j = 0; j < 8; j++) {
                int kg = kt * FBK + j * 8 + (lane & 3) * 2;
                if (kg     > qg0)     sc[j][0] = -1e30f;
                if (kg + 1 > qg0)     sc[j][1] = -1e30f;
                if (kg     > qg0 + 8) sc[j][2] = -1e30f;
                if (kg + 1 > qg0 + 8) sc[j][3] = -1e30f;
            }
        }

        float mx0 = -1e30f, mx1 = -1e30f;
#pragma unroll
        for (int j = 0; j < 8; j++) {
            mx0 = fmaxf(mx0, fmaxf(sc[j][0], sc[j][1]));
            mx1 = fmaxf(mx1, fmaxf(sc[j][2], sc[j][3]));
        }
        mx0 = fmaxf(mx0, __shfl_xor_sync(0xffffffffu, mx0, 1));
        mx0 = fmaxf(mx0, __shfl_xor_sync(0xffffffffu, mx0, 2));
        mx1 = fmaxf(mx1, __shfl_xor_sync(0xffffffffu, mx1, 1));
        mx1 = fmaxf(mx1, __shfl_xor_sync(0xffffffffu, mx1, 2));

        float Mn0 = fmaxf(M0, mx0 * SCALE2);
        float Mn1 = fmaxf(M1, mx1 * SCALE2);
        float a0 = ex2f(M0 - Mn0);
        float a1 = ex2f(M1 - Mn1);
        M0 = Mn0; M1 = Mn1;

        float sum0 = 0.f, sum1 = 0.f;
#pragma unroll
        for (int j = 0; j < 8; j++) {
            sc[j][0] = ex2f(fmaf(sc[j][0], SCALE2, -Mn0));
            sc[j][1] = ex2f(fmaf(sc[j][1], SCALE2, -Mn0));
            sc[j][2] = ex2f(fmaf(sc[j][2], SCALE2, -Mn1));
            sc[j][3] = ex2f(fmaf(sc[j][3], SCALE2, -Mn1));
            sum0 += sc[j][0] + sc[j][1];
            sum1 += sc[j][2] + sc[j][3];
        }
        sum0 += __shfl_xor_sync(0xffffffffu, sum0, 1);
        sum0 += __shfl_xor_sync(0xffffffffu, sum0, 2);
        sum1 += __shfl_xor_sync(0xffffffffu, sum1, 1);
        sum1 += __shfl_xor_sync(0xffffffffu, sum1, 2);
        L0 = L0 * a0 + sum0;
        L1 = L1 * a1 + sum1;

#pragma unroll
        for (int nt = 0; nt < 16; nt++) {
            o[nt][0] *= a0; o[nt][1] *= a0;
            o[nt][2] *= a1; o[nt][3] *= a1;
        }

        uint32_t pf[4][4];
#pragma unroll
        for (int jk = 0; jk < 4; jk++) {
            __half2 h0 = __floats2half2_rn(sc[2*jk][0],   sc[2*jk][1]);
            __half2 h1 = __floats2half2_rn(sc[2*jk][2],   sc[2*jk][3]);
            __half2 h2 = __floats2half2_rn(sc[2*jk+1][0], sc[2*jk+1][1]);
            __half2 h3 = __floats2half2_rn(sc[2*jk+1][2], sc[2*jk+1][3]);
            pf[jk][0] = *(const uint32_t*)&h0;
            pf[jk][1] = *(const uint32_t*)&h1;
            pf[jk][2] = *(const uint32_t*)&h2;
            pf[jk][3] = *(const uint32_t*)&h3;
        }

#pragma unroll
        for (int jk = 0; jk < 4; jk++) {
#pragma unroll
            for (int dn = 0; dn < 8; dn++) {
                uint32_t r0, r1, r2, r3;
                uint32_t addr = sV + ((jk * 16 + (lane & 15)) * FSTR
                                      + dn * 16 + (lane >> 4) * 8) * 2;
                ldsm_x4t(r0, r1, r2, r3, addr);
                uint32_t b0[2] = {r0, r1}, b1[2] = {r2, r3};
                mma16816(o[2 * dn],     pf[jk], b0);
                mma16816(o[2 * dn + 1], pf[jk], b1);
            }
        }
        __syncthreads();
    }

    const int b = bh >> 4, h = bh & 15;
    const float inv0 = 1.f / L0, inv1 = 1.f / L1;
    __half* dst0 = g_yh + (size_t)(b * CL + qg0) * CE + h * CHD;
    __half* dst1 = dst0 + (size_t)8 * CE;
#pragma unroll
    for (int nt = 0; nt < 16; nt++) {
        int d = nt * 8 + (lane & 3) * 2;
        __half2 h0 = __floats2half2_rn(o[nt][0] * inv0, o[nt][1] * inv0);
        __half2 h1 = __floats2half2_rn(o[nt][2] * inv1, o[nt][3] * inv1);
        *(__half2*)(dst0 + d) = h0;
        *(__half2*)(dst1 + d) = h1;
    }
}

// ---------------- host launcher ---------------------------------------------
extern "C" void kernel_launch(void* const* d_in, const int* in_sizes, int n_in,
                              void* d_out, int out_size) {
    const float* x      = (const float*)d_in[0];
    const float* rope   = (const float*)d_in[1];
    const float* w_attn = (const float*)d_in[2];
    const float* w_proj = (const float*)d_in[3];
    float* out = (float*)d_out;

    __half *xh_p, *wah_p, *wph_p, *yh_p;
    cudaGetSymbolAddress((void**)&xh_p,  g_xh);
    cudaGetSymbolAddress((void**)&wah_p, g_wah);
    cudaGetSymbolAddress((void**)&wph_p, g_wph);
    cudaGetSymbolAddress((void**)&yh_p,  g_yh);

    cudaFuncSetAttribute(hgemm_mma, cudaFuncAttributeMaxDynamicSharedMemorySize,
                         GEMM_SMEM);
    cudaFuncSetAttribute(hgemm_qkv, cudaFuncAttributeMaxDynamicSharedMemorySize,
                         GEMM_SMEM);
    cudaFuncSetAttribute(flash_mma, cudaFuncAttributeMaxDynamicSharedMemorySize,
                         FLASH_SMEM);

    // 0) fp32 -> fp16 converts
    f32to16<<<(CM * CE / 4) / 256, 256>>>(x, xh_p);
    f32to16<<<(C3E * CE / 4) / 256, 256>>>(w_attn, wah_p);
    f32to16<<<(CE * CE / 4) / 256, 256>>>(w_proj, wph_p);

    // 1) qkv GEMM with fused rope + head-split -> g_qh/g_kh/g_vh (fp16)
    hgemm_qkv<<<dim3(C3E / BN, CM / BM), 256, GEMM_SMEM>>>(xh_p, wah_p, rope,
                                                           CM, C3E, CE);

    // 2) causal flash attention (HMMA) -> g_yh (fp16)
    flash_mma<<<dim3(CL / FBQ, CB * CH), 128, FLASH_SMEM>>>();

    // 3) out = y @ w_proj^T   [4096, 2048]
    hgemm_mma<<<dim3(CE / BN, CM / BM), 256, GEMM_SMEM>>>(yh_p, wph_p, out,
                                                          CM, CE, CE);
}

// round 17
// speedup vs baseline: 1.1222x; 1.1222x over previous
#include <cuda_runtime.h>
#include <cuda_fp16.h>
#include <cstdint>

#define CB 2
#define CL 2048
#define CE 2048
#define CH 16
#define CHD 128
#define CM (CB*CL)      // 4096
#define C3E (3*CE)      // 6144

// ---------------- scratch (device globals; no allocations allowed) ----------
static __device__ __half g_qh[(size_t)CB*CH*CL*CHD];     // [b,h,l,d] fp16
static __device__ __half g_kh[(size_t)CB*CH*CL*CHD];
static __device__ __half g_vh[(size_t)CB*CH*CL*CHD];
static __device__ __half g_xh[(size_t)CM * CE];          // x in fp16
static __device__ __half g_wah[(size_t)C3E * CE];        // w_attn fp16
static __device__ __half g_wph[(size_t)CE * CE];         // w_proj fp16
static __device__ __half g_yh[(size_t)CM * CE];          // attention out fp16

// ---------------- PTX helpers -------------------------------------------------
__device__ __forceinline__ uint32_t smem_u32(const void* p) {
    uint32_t a;
    asm("{ .reg .u64 t; cvta.to.shared.u64 t, %1; cvt.u32.u64 %0, t; }"
        : "=r"(a) : "l"(p));
    return a;
}
__device__ __forceinline__ void cp16(uint32_t dst, const void* src) {
    asm volatile("cp.async.cg.shared.global [%0], [%1], 16;"
                 :: "r"(dst), "l"(src));
}
#define CP_COMMIT() asm volatile("cp.async.commit_group;" ::: "memory")
#define CP_WAIT(n)  asm volatile("cp.async.wait_group %0;" :: "n"(n) : "memory")

__device__ __forceinline__ void ldsm_x4(uint32_t& r0, uint32_t& r1,
                                        uint32_t& r2, uint32_t& r3, uint32_t a) {
    asm volatile("ldmatrix.sync.aligned.m8n8.x4.shared.b16 {%0,%1,%2,%3}, [%4];"
                 : "=r"(r0), "=r"(r1), "=r"(r2), "=r"(r3) : "r"(a));
}
__device__ __forceinline__ void ldsm_x4t(uint32_t& r0, uint32_t& r1,
                                         uint32_t& r2, uint32_t& r3, uint32_t a) {
    asm volatile("ldmatrix.sync.aligned.m8n8.x4.trans.shared.b16 {%0,%1,%2,%3}, [%4];"
                 : "=r"(r0), "=r"(r1), "=r"(r2), "=r"(r3) : "r"(a));
}
__device__ __forceinline__ void mma16816(float* c, const uint32_t* a,
                                         const uint32_t* b) {
    asm volatile("mma.sync.aligned.m16n8k16.row.col.f32.f16.f16.f32 "
                 "{%0,%1,%2,%3}, {%4,%5,%6,%7}, {%8,%9}, {%0,%1,%2,%3};"
                 : "+f"(c[0]), "+f"(c[1]), "+f"(c[2]), "+f"(c[3])
                 : "r"(a[0]), "r"(a[1]), "r"(a[2]), "r"(a[3]),
                   "r"(b[0]), "r"(b[1]));
}
__device__ __forceinline__ float ex2f(float x) {
    float y;
    asm("ex2.approx.ftz.f32 %0, %1;" : "=f"(y) : "f"(x));
    return y;
}

// ---------------- GEMM: CTA 64x128, 4 warps (2x2), warp tile 32x64, BK=32 ---
// Small CTAs -> 4 CTAs/SM, independent barrier domains (flash-like geometry).
#define BM 64
#define BN 128
#define BK 32
#define ASTR 40
#define STAGES 3
#define ASTAGE (BM * ASTR)                    // 2560 halves
#define BSTAGE (BN * ASTR)                    // 5120 halves
#define STG_HALVES (ASTAGE + BSTAGE)          // 7680
#define GEMM_SMEM (STAGES * STG_HALVES * 2)   // 46080 B

// mainloop producing acc[2][8][4] for warp tile (wm, wn); 32 MMA / 12 ldsm per chunk
// A tile: 64 rows x 4 chunks = 256 cp16 (2/thread); B: 128 x 4 = 512 (4/thread)
#define GEMM_MAINLOOP(Aptr, Bptr, Kdim)                                        \
    float acc[2][8][4];                                                        \
    _Pragma("unroll")                                                          \
    for (int mt = 0; mt < 2; mt++)                                             \
        _Pragma("unroll")                                                      \
        for (int nt = 0; nt < 8; nt++)                                         \
            _Pragma("unroll")                                                  \
            for (int i = 0; i < 4; i++) acc[mt][nt][i] = 0.f;                  \
    auto load_stage = [&](int s, int kc) {                                     \
        const __half* ap = (Aptr) + kc * BK;                                   \
        const __half* bp = (Bptr) + kc * BK;                                   \
        uint32_t da = smBase + (uint32_t)(s * STG_HALVES) * 2;                 \
        uint32_t db = da + ASTAGE * 2;                                         \
        _Pragma("unroll")                                                      \
        for (int i = 0; i < 2; i++) {                                          \
            int idx = i * 128 + tid;                                           \
            int row = idx >> 2, ch = (idx & 3) * 8;                            \
            cp16(da + (row * ASTR + ch) * 2, ap + (size_t)row * (Kdim) + ch);  \
        }                                                                      \
        _Pragma("unroll")                                                      \
        for (int i = 0; i < 4; i++) {                                          \
            int idx = i * 128 + tid;                                           \
            int row = idx >> 2, ch = (idx & 3) * 8;                            \
            cp16(db + (row * ASTR + ch) * 2, bp + (size_t)row * (Kdim) + ch);  \
        }                                                                      \
    };                                                                         \
    const int nk = (Kdim) / BK;                                                \
    _Pragma("unroll")                                                          \
    for (int s = 0; s < STAGES - 1; s++) { load_stage(s, s); CP_COMMIT(); }    \
    const int lrow = lane & 15;                                                \
    const int lcol = (lane >> 4) * 8;                                          \
    int bufc = 0, bufl = STAGES - 1;                                           \
    for (int kc = 0; kc < nk; kc++) {                                          \
        if (kc < nk - 1) CP_WAIT(1);                                           \
        else             CP_WAIT(0);                                           \
        __syncthreads();                                                       \
        if (kc + STAGES - 1 < nk) {                                            \
            load_stage(bufl, kc + STAGES - 1);                                 \
            CP_COMMIT();                                                       \
            if (++bufl == STAGES) bufl = 0;                                    \
        }                                                                      \
        const uint32_t baseA = smBase + (uint32_t)(bufc * STG_HALVES) * 2;     \
        if (++bufc == STAGES) bufc = 0;                                        \
        const uint32_t baseB = baseA + ASTAGE * 2;                             \
        _Pragma("unroll")                                                      \
        for (int ks = 0; ks < 2; ks++) {                                       \
            uint32_t a[2][4], b[4][4];                                         \
            _Pragma("unroll")                                                  \
            for (int mt = 0; mt < 2; mt++) {                                   \
                uint32_t addr = baseA +                                        \
                    ((wm + mt * 16 + lrow) * ASTR + ks * 16 + lcol) * 2;       \
                ldsm_x4(a[mt][0], a[mt][1], a[mt][2], a[mt][3], addr);         \
            }                                                                  \
            _Pragma("unroll")                                                  \
            for (int nh = 0; nh < 4; nh++) {                                   \
                uint32_t addr = baseB +                                        \
                    ((wn + nh * 16 + lrow) * ASTR + ks * 16 + lcol) * 2;       \
                ldsm_x4(b[nh][0], b[nh][1], b[nh][2], b[nh][3], addr);         \
            }                                                                  \
            _Pragma("unroll")                                                  \
            for (int mt = 0; mt < 2; mt++)                                     \
                _Pragma("unroll")                                              \
                for (int nh = 0; nh < 4; nh++) {                               \
                    uint32_t b0[2] = {b[nh][0], b[nh][2]};                     \
                    uint32_t b1[2] = {b[nh][1], b[nh][3]};                     \
                    mma16816(acc[mt][2 * nh],     a[mt], b0);                  \
                    mma16816(acc[mt][2 * nh + 1], a[mt], b1);                  \
                }                                                              \
        }                                                                      \
    }

// ---------------- proj GEMM: C[M,N] = A[M,K]*B[N,K]^T, fp32 out -------------
__global__ __launch_bounds__(128, 4)
void hgemm_mma(const __half* __restrict__ A, const __half* __restrict__ B,
               float* __restrict__ C, int M, int N, int K) {
    extern __shared__ __half smg[];
    const uint32_t smBase = smem_u32(smg);
    const int tid  = threadIdx.x;
    const int lane = tid & 31;
    const int wid  = tid >> 5;
    const int wm   = (wid >> 1) * 32;
    const int wn   = (wid & 1) * 64;
    const int bm   = blockIdx.y * BM;
    const int bn   = blockIdx.x * BN;
    const __half* Ab = A + (size_t)bm * K;
    const __half* Bb = B + (size_t)bn * K;

    GEMM_MAINLOOP(Ab, Bb, K)

    const int tr = lane >> 2;
    const int tc = (lane & 3) * 2;
#pragma unroll
    for (int mt = 0; mt < 2; mt++) {
#pragma unroll
        for (int nt = 0; nt < 8; nt++) {
            int r = bm + wm + mt * 16 + tr;
            int c = bn + wn + nt * 8 + tc;
            *(float2*)(C + (size_t)r * N + c) =
                make_float2(acc[mt][nt][0], acc[mt][nt][1]);
            *(float2*)(C + (size_t)(r + 8) * N + c) =
                make_float2(acc[mt][nt][2], acc[mt][nt][3]);
        }
    }
}

// ---------------- QKV GEMM with fused RoPE + head-split epilogue ------------
// BN=128 tile: which = bn>>11 const per CTA; head = (bn+wn)>>7 const per warp.
__global__ __launch_bounds__(128, 4)
void hgemm_qkv(const __half* __restrict__ A, const __half* __restrict__ B,
               const float* __restrict__ ropeg, int M, int N, int K) {
    extern __shared__ __half smg[];
    const uint32_t smBase = smem_u32(smg);
    const int tid  = threadIdx.x;
    const int lane = tid & 31;
    const int wid  = tid >> 5;
    const int wm   = (wid >> 1) * 32;
    const int wn   = (wid & 1) * 64;
    const int bm   = blockIdx.y * BM;
    const int bn   = blockIdx.x * BN;
    const __half* Ab = A + (size_t)bm * K;
    const __half* Bb = B + (size_t)bn * K;

    GEMM_MAINLOOP(Ab, Bb, K)

    const int tr = lane >> 2;
    const int tc = (lane & 3) * 2;
    const int which = bn >> 11;                   // 0=q, 1=k, 2=v
    const int h     = ((bn + wn) >> 7) & 15;      // constant per warp
    __half* dsts = (which == 0) ? g_qh : (which == 1) ? g_kh : g_vh;

#pragma unroll
    for (int mt = 0; mt < 2; mt++) {
#pragma unroll
        for (int rr = 0; rr < 2; rr++) {
            int r = bm + wm + mt * 16 + tr + rr * 8;
            int l = r & (CL - 1);
            int b = r >> 11;
            __half* base = dsts + ((size_t)(b * CH + h) * CL + l) * CHD;
            const float2* rl = (const float2*)(ropeg + (size_t)l * CHD);
#pragma unroll
            for (int nt = 0; nt < 8; nt++) {
                int d = (wn + nt * 8 + tc) & 127;  // dim within head (even)
                float v0 = acc[mt][nt][rr * 2 + 0];
                float v1 = acc[mt][nt][rr * 2 + 1];
                if (which < 2) {
                    float2 sc = rl[d >> 1];        // x=sin, y=cos
                    float o0 = v0 * sc.y - v1 * sc.x;
                    float o1 = v1 * sc.y + v0 * sc.x;
                    *(__half2*)(base + d) = __floats2half2_rn(o0, o1);
                } else {
                    *(__half2*)(base + d) = __floats2half2_rn(v0, v1);
                }
            }
        }
    }
}

// ---------------- fp32 -> fp16 convert ---------------------------------------
__global__ __launch_bounds__(256)
void f32to16(const float* __restrict__ s, __half* __restrict__ d) {
    int i = blockIdx.x * 256 + threadIdx.x;
    float4 v = *(const float4*)(s + (size_t)i * 4);
    __half2 h0 = __floats2half2_rn(v.x, v.y);
    __half2 h1 = __floats2half2_rn(v.z, v.w);
    uint2 o;
    o.x = *(const uint32_t*)&h0;
    o.y = *(const uint32_t*)&h1;
    *(uint2*)(d + (size_t)i * 4) = o;
}

// ---------------- causal flash attention (HMMA fp16, fp32 accum) -------------
// R8/R12 known-good version: single-buffer KV.
#define FBQ 64
#define FBK 64
#define FSTR 136   // halves per smem row (128 + 8 pad)
#define FLASH_SMEM (3 * 64 * FSTR * 2)   // 52224 B

__global__ __launch_bounds__(128)
void flash_mma() {
    extern __shared__ __half smh[];
    __half* Qs = smh;                 // [64][136]
    __half* Ks = Qs + 64 * FSTR;
    __half* Vs = Ks + 64 * FSTR;

    const int qt   = gridDim.x - 1 - blockIdx.x;   // long CTAs first
    const int bh   = blockIdx.y;
    const int tid  = threadIdx.x;
    const int lane = tid & 31;
    const int wq   = tid >> 5;
    const float SCALE2 = 0.08838834764831845f * 1.4426950408889634f;

    const uint32_t sQ = smem_u32(Qs), sK = smem_u32(Ks), sV = smem_u32(Vs);
    const __half* qbase = g_qh + (size_t)bh * CL * CHD + (size_t)qt * FBQ * CHD;
    const __half* kbase = g_kh + (size_t)bh * CL * CHD;
    const __half* vbase = g_vh + (size_t)bh * CL * CHD;

#pragma unroll
    for (int t = 0; t < 8; t++) {
        int id = t * 128 + tid;
        int row = id >> 4, col = (id & 15) * 8;
        cp16(sQ + (row * FSTR + col) * 2, qbase + (size_t)row * CHD + col);
    }
    CP_COMMIT();
    CP_WAIT(0);
    __syncthreads();

    uint32_t qf[8][4];
#pragma unroll
    for (int ks = 0; ks < 8; ks++) {
        uint32_t addr = sQ + ((wq * 16 + (lane & 15)) * FSTR
                              + ks * 16 + (lane >> 4) * 8) * 2;
        ldsm_x4(qf[ks][0], qf[ks][1], qf[ks][2], qf[ks][3], addr);
    }

    float o[16][4];
#pragma unroll
    for (int nt = 0; nt < 16; nt++)
#pragma unroll
        for (int i = 0; i < 4; i++) o[nt][i] = 0.f;
    float M0 = -1e30f, M1 = -1e30f, L0 = 0.f, L1 = 0.f;

    const int qg0 = qt * FBQ + wq * 16 + (lane >> 2);

    for (int kt = 0; kt <= qt; kt++) {
        const __half* kp = kbase + (size_t)kt * FBK * CHD;
        const __half* vp = vbase + (size_t)kt * FBK * CHD;
#pragma unroll
        for (int t = 0; t < 8; t++) {
            int id = t * 128 + tid;
            int row = id >> 4, col = (id & 15) * 8;
            cp16(sK + (row * FSTR + col) * 2, kp + (size_t)row * CHD + col);
            cp16(sV + (row * FSTR + col) * 2, vp + (size_t)row * CHD + col);
        }
        CP_COMMIT();
        CP_WAIT(0);
        __syncthreads();

        float sc[8][4];
#pragma unroll
        for (int j = 0; j < 8; j++)
#pragma unroll
            for (int i = 0; i < 4; i++) sc[j][i] = 0.f;
#pragma unroll
        for (int ks = 0; ks < 8; ks++) {
#pragma unroll
            for (int jn = 0; jn < 4; jn++) {
                uint32_t r0, r1, r2, r3;
                uint32_t addr = sK + ((jn * 16 + (lane & 15)) * FSTR
                                      + ks * 16 + (lane >> 4) * 8) * 2;
                ldsm_x4(r0, r1, r2, r3, addr);
                uint32_t b0[2] = {r0, r2}, b1[2] = {r1, r3};
                mma16816(sc[2 * jn],     qf[ks], b0);
                mma16816(sc[2 * jn + 1], qf[ks], b1);
            }
        }

        if (kt == qt) {
#pragma unroll
            for (int j = 0; j < 8; j++) {
                int kg = kt * FBK + j * 8 + (lane & 3) * 2;
                if (kg     > qg0)     sc[j][0] = -1e30f;
                if (kg + 1 > qg0)     sc[j][1] = -1e30f;
                if (kg     > qg0 + 8) sc[j][2] = -1e30f;
                if (kg + 1 > qg0 + 8) sc[j][3] = -1e30f;
            }
        }

        float mx0 = -1e30f, mx1 = -1e30f;
#pragma unroll
        for (int j = 0; j < 8; j++) {
            mx0 = fmaxf(mx0, fmaxf(sc[j][0], sc[j][1]));
            mx1 = fmaxf(mx1, fmaxf(sc[j][2], sc[j][3]));
        }
        mx0 = fmaxf(mx0, __shfl_xor_sync(0xffffffffu, mx0, 1));
        mx0 = fmaxf(mx0, __shfl_xor_sync(0xffffffffu, mx0, 2));
        mx1 = fmaxf(mx1, __shfl_xor_sync(0xffffffffu, mx1, 1));
        mx1 = fmaxf(mx1, __shfl_xor_sync(0xffffffffu, mx1, 2));

        float Mn0 = fmaxf(M0, mx0 * SCALE2);
        float Mn1 = fmaxf(M1, mx1 * SCALE2);
        float a0 = ex2f(M0 - Mn0);
        float a1 = ex2f(M1 - Mn1);
        M0 = Mn0; M1 = Mn1;

        float sum0 = 0.f, sum1 = 0.f;
#pragma unroll
        for (int j = 0; j < 8; j++) {
            sc[j][0] = ex2f(fmaf(sc[j][0], SCALE2, -Mn0));
            sc[j][1] = ex2f(fmaf(sc[j][1], SCALE2, -Mn0));
            sc[j][2] = ex2f(fmaf(sc[j][2], SCALE2, -Mn1));
            sc[j][3] = ex2f(fmaf(sc[j][3], SCALE2, -Mn1));
            sum0 += sc[j][0] + sc[j][1];
            sum1 += sc[j][2] + sc[j][3];
        }
        sum0 += __shfl_xor_sync(0xffffffffu, sum0, 1);
        sum0 += __shfl_xor_sync(0xffffffffu, sum0, 2);
        sum1 += __shfl_xor_sync(0xffffffffu, sum1, 1);
        sum1 += __shfl_xor_sync(0xffffffffu, sum1, 2);
        L0 = L0 * a0 + sum0;
        L1 = L1 * a1 + sum1;

#pragma unroll
        for (int nt = 0; nt < 16; nt++) {
            o[nt][0] *= a0; o[nt][1] *= a0;
            o[nt][2] *= a1; o[nt][3] *= a1;
        }

        uint32_t pf[4][4];
#pragma unroll
        for (int jk = 0; jk < 4; jk++) {
            __half2 h0 = __floats2half2_rn(sc[2*jk][0],   sc[2*jk][1]);
            __half2 h1 = __floats2half2_rn(sc[2*jk][2],   sc[2*jk][3]);
            __half2 h2 = __floats2half2_rn(sc[2*jk+1][0], sc[2*jk+1][1]);
            __half2 h3 = __floats2half2_rn(sc[2*jk+1][2], sc[2*jk+1][3]);
            pf[jk][0] = *(const uint32_t*)&h0;
            pf[jk][1] = *(const uint32_t*)&h1;
            pf[jk][2] = *(const uint32_t*)&h2;
            pf[jk][3] = *(const uint32_t*)&h3;
        }

#pragma unroll
        for (int jk = 0; jk < 4; jk++) {
#pragma unroll
            for (int dn = 0; dn < 8; dn++) {
                uint32_t r0, r1, r2, r3;
                uint32_t addr = sV + ((jk * 16 + (lane & 15)) * FSTR
                                      + dn * 16 + (lane >> 4) * 8) * 2;
                ldsm_x4t(r0, r1, r2, r3, addr);
                uint32_t b0[2] = {r0, r1}, b1[2] = {r2, r3};
                mma16816(o[2 * dn],     pf[jk], b0);
                mma16816(o[2 * dn + 1], pf[jk], b1);
            }
        }
        __syncthreads();
    }

    const int b = bh >> 4, h = bh & 15;
    const float inv0 = 1.f / L0, inv1 = 1.f / L1;
    __half* dst0 = g_yh + (size_t)(b * CL + qg0) * CE + h * CHD;
    __half* dst1 = dst0 + (size_t)8 * CE;
#pragma unroll
    for (int nt = 0; nt < 16; nt++) {
        int d = nt * 8 + (lane & 3) * 2;
        __half2 h0 = __floats2half2_rn(o[nt][0] * inv0, o[nt][1] * inv0);
        __half2 h1 = __floats2half2_rn(o[nt][2] * inv1, o[nt][3] * inv1);
        *(__half2*)(dst0 + d) = h0;
        *(__half2*)(dst1 + d) = h1;
    }
}

// ---------------- host launcher ---------------------------------------------
extern "C" void kernel_launch(void* const* d_in, const int* in_sizes, int n_in,
                              void* d_out, int out_size) {
    const float* x      = (const float*)d_in[0];
    const float* rope   = (const float*)d_in[1];
    const float* w_attn = (const float*)d_in[2];
    const float* w_proj = (const float*)d_in[3];
    float* out = (float*)d_out;

    __half *xh_p, *wah_p, *wph_p, *yh_p;
    cudaGetSymbolAddress((void**)&xh_p,  g_xh);
    cudaGetSymbolAddress((void**)&wah_p, g_wah);
    cudaGetSymbolAddress((void**)&wph_p, g_wph);
    cudaGetSymbolAddress((void**)&yh_p,  g_yh);

    cudaFuncSetAttribute(hgemm_mma, cudaFuncAttributeMaxDynamicSharedMemorySize,
                         GEMM_SMEM);
    cudaFuncSetAttribute(hgemm_qkv, cudaFuncAttributeMaxDynamicSharedMemorySize,
                         GEMM_SMEM);
    cudaFuncSetAttribute(flash_mma, cudaFuncAttributeMaxDynamicSharedMemorySize,
                         FLASH_SMEM);

    // 0) fp32 -> fp16 converts
    f32to16<<<(CM * CE / 4) / 256, 256>>>(x, xh_p);
    f32to16<<<(C3E * CE / 4) / 256, 256>>>(w_attn, wah_p);
    f32to16<<<(CE * CE / 4) / 256, 256>>>(w_proj, wph_p);

    // 1) qkv GEMM with fused rope + head-split -> g_qh/g_kh/g_vh (fp16)
    hgemm_qkv<<<dim3(C3E / BN, CM / BM), 128, GEMM_SMEM>>>(xh_p, wah_p, rope,
                                                           CM, C3E, CE);

    // 2) causal flash attention (HMMA) -> g_yh (fp16)
    flash_mma<<<dim3(CL / FBQ, CB * CH), 128, FLASH_SMEM>>>();

    // 3) out = y @ w_proj^T   [4096, 2048]
    hgemm_mma<<<dim3(CE / BN, CM / BM), 128, GEMM_SMEM>>>(yh_p, wph_p, out,
                                                          CM, CE, CE);
}